// round 16
// baseline (speedup 1.0000x reference)
#include <cuda_runtime.h>
#include <cuda_bf16.h>

// dRMSD, L=2048, B=8.
// R16 = R15 (TS=256, 288 blocks, bf16x2 Gram hot loop) + accumulation moved
// from scalar FADD (fma pipe, the measured 61%-busy wall) to packed f32x2
// adds on the wide pipe (idle). Per GROUP the fma pipe drops 22->18 cycles.

#define BATCH  8
#define NPTS   2047
#define NPAD   2048
#define TS     256
#define NT     (NPAD / TS)                 // 8
#define TPAIRS (NT * (NT + 1) / 2)         // 36
#define NBLK   (BATCH * TPAIRS)            // 288
#define TPB    256

__device__ __align__(16) __nv_bfloat16 g_jb[BATCH][8][NPAD]; // -2x(3),|x|^2,-2y(3),|y|^2
__device__ __align__(16) __nv_bfloat16 g_ia[BATCH][NPAD][8]; // x(3),|x|^2,y(3),|y|^2 (AoS)
__device__ float    g_part[NBLK];
__device__ float    g_aux[BATCH][NT][9];
__device__ unsigned g_count;

typedef unsigned long long u64;

__device__ __forceinline__ float sqrt_abs(float x) {
    float r; asm("sqrt.approx.f32 %0, %1;" : "=f"(r) : "f"(fabsf(x))); return r;
}
__device__ __forceinline__ __nv_bfloat162 u2b(unsigned u) {
    __nv_bfloat162 r; *reinterpret_cast<unsigned*>(&r) = u; return r;
}
__device__ __forceinline__ unsigned b2u(__nv_bfloat162 v) {
    return *reinterpret_cast<unsigned*>(&v);
}
__device__ __forceinline__ unsigned bf16_of(float f) {
    __nv_bfloat16 h = __float2bfloat16(f);
    return (unsigned)*reinterpret_cast<unsigned short*>(&h);
}
__device__ __forceinline__ u64 pack2(float lo, float hi) {
    u64 r; asm("mov.b64 %0, {%1, %2};" : "=l"(r) : "f"(lo), "f"(hi)); return r;
}
__device__ __forceinline__ void unpack2(u64 v, float& lo, float& hi) {
    asm("mov.b64 {%0, %1}, %2;" : "=f"(lo), "=f"(hi) : "l"(v));
}
__device__ __forceinline__ u64 add2(u64 a, u64 b) {   // wide pipe
    u64 r; asm("add.rn.f32x2 %0, %1, %2;" : "=l"(r) : "l"(a), "l"(b)); return r;
}

// ---------------- prep: coalesced transpose + operand precompute ------------
#define PREP_T 384
__global__ __launch_bounds__(PREP_T) void prep_kernel(
    const float* __restrict__ x, const float* __restrict__ y)
{
    __shared__ float sx[1536], sy[1536];   // 64 rows x 8 batches x 3 coords
    int r0 = blockIdx.x * 64;              // 32 blocks cover 2048 rows
    int tid = threadIdx.x;

    reinterpret_cast<float4*>(sx)[tid] =
        reinterpret_cast<const float4*>(x + r0 * 24)[tid];
    reinterpret_cast<float4*>(sy)[tid] =
        reinterpret_cast<const float4*>(y + r0 * 24)[tid];
    __syncthreads();

    for (int p = tid; p < 512; p += PREP_T) {   // 64 rows x 8 batches
        int b  = p >> 6;
        int rl = p & 63;
        int row = r0 + rl;
        if (row < 1) continue;                  // row 0 dropped by the mask
        int s = row - 1;                        // gathered index 0..2046
        int o = (rl * 8 + b) * 3;
        float x0 = sx[o], x1 = sx[o + 1], x2 = sx[o + 2];
        float y0 = sy[o], y1 = sy[o + 1], y2 = sy[o + 2];
        float px = x0 * x0 + x1 * x1 + x2 * x2;
        float py = y0 * y0 + y1 * y1 + y2 * y2;
        g_jb[b][0][s] = __float2bfloat16(-2.f * x0);
        g_jb[b][1][s] = __float2bfloat16(-2.f * x1);
        g_jb[b][2][s] = __float2bfloat16(-2.f * x2);
        g_jb[b][3][s] = __float2bfloat16(px);
        g_jb[b][4][s] = __float2bfloat16(-2.f * y0);
        g_jb[b][5][s] = __float2bfloat16(-2.f * y1);
        g_jb[b][6][s] = __float2bfloat16(-2.f * y2);
        g_jb[b][7][s] = __float2bfloat16(py);
        uint4 pack;
        pack.x = bf16_of(x0) | (bf16_of(x1) << 16);
        pack.y = bf16_of(x2) | (bf16_of(px) << 16);
        pack.z = bf16_of(y0) | (bf16_of(y1) << 16);
        pack.w = bf16_of(y2) | (bf16_of(py) << 16);
        *reinterpret_cast<uint4*>(&g_ia[b][s][0]) = pack;
    }
}

// ---------------- main ------------------------------------------------------
__global__ __launch_bounds__(TPB, 2) void drmsd_kernel(
    const float* __restrict__ x, const float* __restrict__ y,
    float* __restrict__ out)
{
    int bid = blockIdx.x;
    int b = bid / TPAIRS;
    int t = bid - b * TPAIRS;
    // triangular decode, NT=8
    int ti = (int)((17.0f - sqrtf((float)(289 - 8 * t))) * 0.5f);
    if (ti * (17 - ti) / 2 > t) ti--;
    if ((ti + 1) * (16 - ti) / 2 <= t) ti++;
    int tj = ti + (t - ti * (17 - ti) / 2);
    bool diag = (ti == tj);

    __shared__ __align__(16) __nv_bfloat16 sjh[8][TS];
    int tid = threadIdx.x;

    // ---- j-tile: one coalesced LDG.128 + STS.128 per thread ----
    {
        int ch  = tid >> 5;
        int t32 = tid & 31;
        const uint4* src = reinterpret_cast<const uint4*>(&g_jb[b][ch][tj * TS]);
        reinterpret_cast<uint4*>(&sjh[ch][0])[t32] = src[t32];
    }

    // ---- per-tile moments (diagonal blocks only; exact fp32 path) ----
    if (diag) {
        float ix0 = 0.f, ix1 = 0.f, ix2 = 0.f, iy0 = 0.f, iy1 = 0.f, iy2 = 0.f;
        int s = ti * TS + tid;
        if (s < NPTS) {
            int base = ((s + 1) * BATCH + b) * 3;
            ix0 = x[base]; ix1 = x[base + 1]; ix2 = x[base + 2];
            iy0 = y[base]; iy1 = y[base + 1]; iy2 = y[base + 2];
        }
        float ipx = ix0 * ix0 + ix1 * ix1 + ix2 * ix2;
        float ipy = iy0 * iy0 + iy1 * iy1 + iy2 * iy2;
        float v[9] = { ipx, ix0, ix1, ix2, ipy, iy0, iy1, iy2, sqrtf(ipx * ipy) };
        #pragma unroll
        for (int off = 16; off > 0; off >>= 1)
            #pragma unroll
            for (int q = 0; q < 9; q++)
                v[q] += __shfl_down_sync(0xffffffffu, v[q], off);
        __shared__ float waux[TPB / 32][9];
        if ((tid & 31) == 0)
            #pragma unroll
            for (int q = 0; q < 9; q++) waux[tid >> 5][q] = v[q];
        __syncthreads();
        if (tid == 0) {
            #pragma unroll
            for (int q = 0; q < 9; q++) {
                float s9 = 0.f;
                #pragma unroll
                for (int ww = 0; ww < TPB / 32; ww++) s9 += waux[ww][q];
                g_aux[b][ti][q] = s9;
            }
        }
    }

    // ---- i-splats: 2 LDG.128 (AoS) + PRMT dups ----
    int w = tid >> 5, lane = tid & 31;
    int jbase = (w & 1) * 128;
    int s0 = ti * TS + (w >> 1) * 64 + lane;
    int s1 = s0 + 32;

    uint4 ia = *reinterpret_cast<const uint4*>(&g_ia[b][s0][0]);
    uint4 ib = *reinterpret_cast<const uint4*>(&g_ia[b][s1][0]);

    __nv_bfloat162 X00 = u2b(__byte_perm(ia.x, ia.x, 0x1010));
    __nv_bfloat162 X01 = u2b(__byte_perm(ia.x, ia.x, 0x3232));
    __nv_bfloat162 X02 = u2b(__byte_perm(ia.y, ia.y, 0x1010));
    __nv_bfloat162 PX0 = u2b(__byte_perm(ia.y, ia.y, 0x3232));
    __nv_bfloat162 Y00 = u2b(__byte_perm(ia.z, ia.z, 0x1010));
    __nv_bfloat162 Y01 = u2b(__byte_perm(ia.z, ia.z, 0x3232));
    __nv_bfloat162 Y02 = u2b(__byte_perm(ia.w, ia.w, 0x1010));
    __nv_bfloat162 PY0 = u2b(__byte_perm(ia.w, ia.w, 0x3232));
    __nv_bfloat162 X10 = u2b(__byte_perm(ib.x, ib.x, 0x1010));
    __nv_bfloat162 X11 = u2b(__byte_perm(ib.x, ib.x, 0x3232));
    __nv_bfloat162 X12 = u2b(__byte_perm(ib.y, ib.y, 0x1010));
    __nv_bfloat162 PX1 = u2b(__byte_perm(ib.y, ib.y, 0x3232));
    __nv_bfloat162 Y10 = u2b(__byte_perm(ib.z, ib.z, 0x1010));
    __nv_bfloat162 Y11 = u2b(__byte_perm(ib.z, ib.z, 0x3232));
    __nv_bfloat162 Y12 = u2b(__byte_perm(ib.w, ib.w, 0x1010));
    __nv_bfloat162 PY1 = u2b(__byte_perm(ib.w, ib.w, 0x3232));

    __syncthreads();   // sjh ready

    u64 acc0 = 0ull, acc1 = 0ull;   // packed f32x2 accumulators (wide pipe)

    // GROUP = 1 i vs 2 j's; sqrt results accumulated via f32x2 add (wide pipe)
    #define GROUP(CW0, CW1, CW2, CWN, DW0, DW1, DW2, DWN, XX0, XX1, XX2, PPX, YY0, YY1, YY2, PPY, ACC) { \
        __nv_bfloat162 tx_ = __hfma2(u2b(CW0), XX0, __hfma2(u2b(CW1), XX1,      \
                              __hfma2(u2b(CW2), XX2, __hadd2(u2b(CWN), PPX)))); \
        __nv_bfloat162 ty_ = __hfma2(u2b(DW0), YY0, __hfma2(u2b(DW1), YY1,      \
                              __hfma2(u2b(DW2), YY2, __hadd2(u2b(DWN), PPY)))); \
        unsigned pv_ = b2u(__hmul2(tx_, ty_));                                  \
        float slo_ = sqrt_abs(__uint_as_float(pv_ << 16));                      \
        float shi_ = sqrt_abs(__uint_as_float(pv_ & 0xffff0000u));              \
        ACC = add2(ACC, pack2(slo_, shi_));                                     \
    }

    #pragma unroll 2
    for (int jc = 0; jc < 16; jc++) {      // 8 j's per iteration, 128 total
        int jo = jbase + jc * 8;           // warp-uniform -> LDS broadcast
        uint4 c0 = *reinterpret_cast<const uint4*>(&sjh[0][jo]);
        uint4 c1 = *reinterpret_cast<const uint4*>(&sjh[1][jo]);
        uint4 c2 = *reinterpret_cast<const uint4*>(&sjh[2][jo]);
        uint4 cn = *reinterpret_cast<const uint4*>(&sjh[3][jo]);
        uint4 d0 = *reinterpret_cast<const uint4*>(&sjh[4][jo]);
        uint4 d1 = *reinterpret_cast<const uint4*>(&sjh[5][jo]);
        uint4 d2 = *reinterpret_cast<const uint4*>(&sjh[6][jo]);
        uint4 dn = *reinterpret_cast<const uint4*>(&sjh[7][jo]);

        GROUP(c0.x, c1.x, c2.x, cn.x, d0.x, d1.x, d2.x, dn.x,
              X00, X01, X02, PX0, Y00, Y01, Y02, PY0, acc0)
        GROUP(c0.x, c1.x, c2.x, cn.x, d0.x, d1.x, d2.x, dn.x,
              X10, X11, X12, PX1, Y10, Y11, Y12, PY1, acc1)
        GROUP(c0.y, c1.y, c2.y, cn.y, d0.y, d1.y, d2.y, dn.y,
              X00, X01, X02, PX0, Y00, Y01, Y02, PY0, acc0)
        GROUP(c0.y, c1.y, c2.y, cn.y, d0.y, d1.y, d2.y, dn.y,
              X10, X11, X12, PX1, Y10, Y11, Y12, PY1, acc1)
        GROUP(c0.z, c1.z, c2.z, cn.z, d0.z, d1.z, d2.z, dn.z,
              X00, X01, X02, PX0, Y00, Y01, Y02, PY0, acc0)
        GROUP(c0.z, c1.z, c2.z, cn.z, d0.z, d1.z, d2.z, dn.z,
              X10, X11, X12, PX1, Y10, Y11, Y12, PY1, acc1)
        GROUP(c0.w, c1.w, c2.w, cn.w, d0.w, d1.w, d2.w, dn.w,
              X00, X01, X02, PX0, Y00, Y01, Y02, PY0, acc0)
        GROUP(c0.w, c1.w, c2.w, cn.w, d0.w, d1.w, d2.w, dn.w,
              X10, X11, X12, PX1, Y10, Y11, Y12, PY1, acc1)
    }
    #undef GROUP

    float v0l, v0h, v1l, v1h;
    unpack2(acc0, v0l, v0h);
    unpack2(acc1, v1l, v1h);
    float val = (v0l + v0h) + (v1l + v1h);

    // deterministic block reduce (8 warps)
    #pragma unroll
    for (int off = 16; off > 0; off >>= 1)
        val += __shfl_down_sync(0xffffffffu, val, off);
    __shared__ float wsum[TPB / 32];
    if ((tid & 31) == 0) wsum[tid >> 5] = val;
    __syncthreads();
    if (tid == 0) {
        float s = 0.f;
        #pragma unroll
        for (int ww = 0; ww < TPB / 32; ww++) s += wsum[ww];
        g_part[bid] = diag ? s : 2.0f * s;
    }

    // ---- last-block final reduction ----
    __shared__ bool isLast;
    if (tid == 0) {
        __threadfence();
        unsigned v = atomicAdd(&g_count, 1u);
        isLast = (v == (unsigned)(gridDim.x - 1));
    }
    __syncthreads();
    if (!isLast) return;
    __threadfence();

    int b2 = tid >> 5;                  // 0..7 (batch per warp)
    int l  = tid & 31;

    float wacc = 0.f;
    for (int k = l; k < TPAIRS; k += 32)
        wacc += g_part[b2 * TPAIRS + k];
    float a[9];
    #pragma unroll
    for (int q = 0; q < 9; q++)
        a[q] = (l < NT) ? g_aux[b2][l][q] : 0.f;

    #pragma unroll
    for (int off = 16; off > 0; off >>= 1) {
        wacc += __shfl_down_sync(0xffffffffu, wacc, off);
        #pragma unroll
        for (int q = 0; q < 9; q++)
            a[q] += __shfl_down_sync(0xffffffffu, a[q], off);
    }

    __shared__ float norms[BATCH];
    if (l == 0) {
        float n = (float)NPTS;
        float T = 2.0f * (n * a[0] - (a[1] * a[1] + a[2] * a[2] + a[3] * a[3]))
                + 2.0f * (n * a[4] - (a[5] * a[5] + a[6] * a[6] + a[7] * a[7]));
        float W = wacc - 2.0f * a[8];
        float S = T - 2.0f * W;
        if (S < 0.f) S = 0.f;
        norms[b2] = sqrtf(S);
    }
    __syncthreads();
    if (tid == 0) {
        float tot = 0.f;
        #pragma unroll
        for (int i = 0; i < BATCH; i++) tot += norms[i];
        float n = (float)NPTS;
        out[0] = tot / sqrtf(n * n - n) / (float)BATCH;
        g_count = 0;
    }
}

extern "C" void kernel_launch(void* const* d_in, const int* in_sizes, int n_in,
                              void* d_out, int out_size) {
    const float* x = (const float*)d_in[0];
    const float* y = (const float*)d_in[1];
    (void)in_sizes; (void)n_in; (void)out_size;
    prep_kernel<<<32, PREP_T>>>(x, y);
    drmsd_kernel<<<NBLK, TPB>>>(x, y, (float*)d_out);
}

// round 17
// speedup vs baseline: 1.0050x; 1.0050x over previous
#include <cuda_runtime.h>
#include <cuda_bf16.h>

// dRMSD, L=2048, B=8.
// R17 = R16 hot loop, SINGLE kernel: prep distributed across all 288 blocks
// (8 rows each, coalesced span load) + global arrive/spin barrier before the
// operand arrays are read. Deadlock-free: bounds(256,2) -> capacity 296 >=
// grid 288, whole grid co-resident. Diag moments (independent of prep) are
// computed before the spin to hide barrier wait. Removes the separate prep
// launch + gap (~3 us measured in R16).

#define BATCH  8
#define NPTS   2047
#define NPAD   2048
#define TS     256
#define NT     (NPAD / TS)                 // 8
#define TPAIRS (NT * (NT + 1) / 2)         // 36
#define NBLK   (BATCH * TPAIRS)            // 288
#define TPB    256
#define PREP_ROWS 8                        // rows per block (288*8 >= 2048)

__device__ __align__(16) __nv_bfloat16 g_jb[BATCH][8][NPAD]; // -2x(3),|x|^2,-2y(3),|y|^2
__device__ __align__(16) __nv_bfloat16 g_ia[BATCH][NPAD][8]; // x(3),|x|^2,y(3),|y|^2 (AoS)
__device__ float    g_part[NBLK];
__device__ float    g_aux[BATCH][NT][9];
__device__ unsigned g_count;               // final-reduction arrival counter
__device__ unsigned g_prep;                // prep-phase arrival counter

typedef unsigned long long u64;

__device__ __forceinline__ float sqrt_abs(float x) {
    float r; asm("sqrt.approx.f32 %0, %1;" : "=f"(r) : "f"(fabsf(x))); return r;
}
__device__ __forceinline__ __nv_bfloat162 u2b(unsigned u) {
    __nv_bfloat162 r; *reinterpret_cast<unsigned*>(&r) = u; return r;
}
__device__ __forceinline__ unsigned b2u(__nv_bfloat162 v) {
    return *reinterpret_cast<unsigned*>(&v);
}
__device__ __forceinline__ unsigned bf16_of(float f) {
    __nv_bfloat16 h = __float2bfloat16(f);
    return (unsigned)*reinterpret_cast<unsigned short*>(&h);
}
__device__ __forceinline__ u64 pack2(float lo, float hi) {
    u64 r; asm("mov.b64 %0, {%1, %2};" : "=l"(r) : "f"(lo), "f"(hi)); return r;
}
__device__ __forceinline__ void unpack2(u64 v, float& lo, float& hi) {
    asm("mov.b64 {%0, %1}, %2;" : "=f"(lo), "=f"(hi) : "l"(v));
}
__device__ __forceinline__ u64 add2(u64 a, u64 b) {   // wide pipe
    u64 r; asm("add.rn.f32x2 %0, %1, %2;" : "=l"(r) : "l"(a), "l"(b)); return r;
}

__global__ __launch_bounds__(TPB, 2) void drmsd_kernel(
    const float* __restrict__ x, const float* __restrict__ y,
    float* __restrict__ out)
{
    int bid = blockIdx.x;
    int b = bid / TPAIRS;
    int t = bid - b * TPAIRS;
    // triangular decode, NT=8
    int ti = (int)((17.0f - sqrtf((float)(289 - 8 * t))) * 0.5f);
    if (ti * (17 - ti) / 2 > t) ti--;
    if ((ti + 1) * (16 - ti) / 2 <= t) ti++;
    int tj = ti + (t - ti * (17 - ti) / 2);
    bool diag = (ti == tj);

    __shared__ __align__(16) __nv_bfloat16 sjh[8][TS];
    __shared__ float spx[2 * PREP_ROWS * 24];   // x span | y span (192+192)
    int tid = threadIdx.x;

    // ======== PHASE 0: this block's prep share (8 rows, coalesced) ========
    {
        int r0 = bid * PREP_ROWS;               // rows [r0, r0+8)
        int nrows = (r0 < NPAD) ? ((r0 + PREP_ROWS <= NPAD) ? PREP_ROWS : NPAD - r0) : 0;
        int nf = nrows * 24;                    // floats per tensor span
        for (int k = tid; k * 4 < nf; k += TPB)
            reinterpret_cast<float4*>(spx)[k] =
                reinterpret_cast<const float4*>(x + r0 * 24)[k];
        for (int k = tid; k * 4 < nf; k += TPB)
            reinterpret_cast<float4*>(spx + PREP_ROWS * 24)[k] =
                reinterpret_cast<const float4*>(y + r0 * 24)[k];
        __syncthreads();
        if (tid < nrows * 8) {                  // one thread per (row,batch)
            int rl = tid >> 3;
            int bb = tid & 7;
            int row = r0 + rl;
            if (row >= 1) {
                int s = row - 1;
                int o = tid * 3;                // (rl*8+bb)*3
                float x0 = spx[o], x1 = spx[o + 1], x2 = spx[o + 2];
                float y0 = spx[PREP_ROWS * 24 + o];
                float y1 = spx[PREP_ROWS * 24 + o + 1];
                float y2 = spx[PREP_ROWS * 24 + o + 2];
                float px = x0 * x0 + x1 * x1 + x2 * x2;
                float py = y0 * y0 + y1 * y1 + y2 * y2;
                g_jb[bb][0][s] = __float2bfloat16(-2.f * x0);
                g_jb[bb][1][s] = __float2bfloat16(-2.f * x1);
                g_jb[bb][2][s] = __float2bfloat16(-2.f * x2);
                g_jb[bb][3][s] = __float2bfloat16(px);
                g_jb[bb][4][s] = __float2bfloat16(-2.f * y0);
                g_jb[bb][5][s] = __float2bfloat16(-2.f * y1);
                g_jb[bb][6][s] = __float2bfloat16(-2.f * y2);
                g_jb[bb][7][s] = __float2bfloat16(py);
                uint4 pk;
                pk.x = bf16_of(x0) | (bf16_of(x1) << 16);
                pk.y = bf16_of(x2) | (bf16_of(px) << 16);
                pk.z = bf16_of(y0) | (bf16_of(y1) << 16);
                pk.w = bf16_of(y2) | (bf16_of(py) << 16);
                *reinterpret_cast<uint4*>(&g_ia[bb][s][0]) = pk;
            }
        }
        __syncthreads();
        if (tid == 0) {
            __threadfence();
            atomicAdd(&g_prep, 1u);
        }
    }

    // ---- diag moments: independent of prep (reads x,y) — hides spin wait ----
    if (diag) {
        float ix0 = 0.f, ix1 = 0.f, ix2 = 0.f, iy0 = 0.f, iy1 = 0.f, iy2 = 0.f;
        int s = ti * TS + tid;
        if (s < NPTS) {
            int base = ((s + 1) * BATCH + b) * 3;
            ix0 = x[base]; ix1 = x[base + 1]; ix2 = x[base + 2];
            iy0 = y[base]; iy1 = y[base + 1]; iy2 = y[base + 2];
        }
        float ipx = ix0 * ix0 + ix1 * ix1 + ix2 * ix2;
        float ipy = iy0 * iy0 + iy1 * iy1 + iy2 * iy2;
        float v[9] = { ipx, ix0, ix1, ix2, ipy, iy0, iy1, iy2, sqrtf(ipx * ipy) };
        #pragma unroll
        for (int off = 16; off > 0; off >>= 1)
            #pragma unroll
            for (int q = 0; q < 9; q++)
                v[q] += __shfl_down_sync(0xffffffffu, v[q], off);
        __shared__ float waux[TPB / 32][9];
        if ((tid & 31) == 0)
            #pragma unroll
            for (int q = 0; q < 9; q++) waux[tid >> 5][q] = v[q];
        __syncthreads();
        if (tid == 0) {
            #pragma unroll
            for (int q = 0; q < 9; q++) {
                float s9 = 0.f;
                #pragma unroll
                for (int ww = 0; ww < TPB / 32; ww++) s9 += waux[ww][q];
                g_aux[b][ti][q] = s9;
            }
        }
    }

    // ======== global barrier: wait until all 288 blocks finished prep ========
    if (tid == 0) {
        while (atomicAdd(&g_prep, 0u) < (unsigned)gridDim.x) { }
        __threadfence();
    }
    __syncthreads();

    // ---- j-tile: one coalesced LDG.128 + STS.128 per thread ----
    {
        int ch  = tid >> 5;
        int t32 = tid & 31;
        const uint4* src = reinterpret_cast<const uint4*>(&g_jb[b][ch][tj * TS]);
        reinterpret_cast<uint4*>(&sjh[ch][0])[t32] = src[t32];
    }

    // ---- i-splats: 2 LDG.128 (AoS) + PRMT dups ----
    int w = tid >> 5, lane = tid & 31;
    int jbase = (w & 1) * 128;
    int s0 = ti * TS + (w >> 1) * 64 + lane;
    int s1 = s0 + 32;

    uint4 ia = *reinterpret_cast<const uint4*>(&g_ia[b][s0][0]);
    uint4 ib = *reinterpret_cast<const uint4*>(&g_ia[b][s1][0]);

    __nv_bfloat162 X00 = u2b(__byte_perm(ia.x, ia.x, 0x1010));
    __nv_bfloat162 X01 = u2b(__byte_perm(ia.x, ia.x, 0x3232));
    __nv_bfloat162 X02 = u2b(__byte_perm(ia.y, ia.y, 0x1010));
    __nv_bfloat162 PX0 = u2b(__byte_perm(ia.y, ia.y, 0x3232));
    __nv_bfloat162 Y00 = u2b(__byte_perm(ia.z, ia.z, 0x1010));
    __nv_bfloat162 Y01 = u2b(__byte_perm(ia.z, ia.z, 0x3232));
    __nv_bfloat162 Y02 = u2b(__byte_perm(ia.w, ia.w, 0x1010));
    __nv_bfloat162 PY0 = u2b(__byte_perm(ia.w, ia.w, 0x3232));
    __nv_bfloat162 X10 = u2b(__byte_perm(ib.x, ib.x, 0x1010));
    __nv_bfloat162 X11 = u2b(__byte_perm(ib.x, ib.x, 0x3232));
    __nv_bfloat162 X12 = u2b(__byte_perm(ib.y, ib.y, 0x1010));
    __nv_bfloat162 PX1 = u2b(__byte_perm(ib.y, ib.y, 0x3232));
    __nv_bfloat162 Y10 = u2b(__byte_perm(ib.z, ib.z, 0x1010));
    __nv_bfloat162 Y11 = u2b(__byte_perm(ib.z, ib.z, 0x3232));
    __nv_bfloat162 Y12 = u2b(__byte_perm(ib.w, ib.w, 0x1010));
    __nv_bfloat162 PY1 = u2b(__byte_perm(ib.w, ib.w, 0x3232));

    __syncthreads();   // sjh ready

    u64 acc0 = 0ull, acc1 = 0ull;   // packed f32x2 accumulators (wide pipe)

    #define GROUP(CW0, CW1, CW2, CWN, DW0, DW1, DW2, DWN, XX0, XX1, XX2, PPX, YY0, YY1, YY2, PPY, ACC) { \
        __nv_bfloat162 tx_ = __hfma2(u2b(CW0), XX0, __hfma2(u2b(CW1), XX1,      \
                              __hfma2(u2b(CW2), XX2, __hadd2(u2b(CWN), PPX)))); \
        __nv_bfloat162 ty_ = __hfma2(u2b(DW0), YY0, __hfma2(u2b(DW1), YY1,      \
                              __hfma2(u2b(DW2), YY2, __hadd2(u2b(DWN), PPY)))); \
        unsigned pv_ = b2u(__hmul2(tx_, ty_));                                  \
        float slo_ = sqrt_abs(__uint_as_float(pv_ << 16));                      \
        float shi_ = sqrt_abs(__uint_as_float(pv_ & 0xffff0000u));              \
        ACC = add2(ACC, pack2(slo_, shi_));                                     \
    }

    #pragma unroll 2
    for (int jc = 0; jc < 16; jc++) {      // 8 j's per iteration, 128 total
        int jo = jbase + jc * 8;           // warp-uniform -> LDS broadcast
        uint4 c0 = *reinterpret_cast<const uint4*>(&sjh[0][jo]);
        uint4 c1 = *reinterpret_cast<const uint4*>(&sjh[1][jo]);
        uint4 c2 = *reinterpret_cast<const uint4*>(&sjh[2][jo]);
        uint4 cn = *reinterpret_cast<const uint4*>(&sjh[3][jo]);
        uint4 d0 = *reinterpret_cast<const uint4*>(&sjh[4][jo]);
        uint4 d1 = *reinterpret_cast<const uint4*>(&sjh[5][jo]);
        uint4 d2 = *reinterpret_cast<const uint4*>(&sjh[6][jo]);
        uint4 dn = *reinterpret_cast<const uint4*>(&sjh[7][jo]);

        GROUP(c0.x, c1.x, c2.x, cn.x, d0.x, d1.x, d2.x, dn.x,
              X00, X01, X02, PX0, Y00, Y01, Y02, PY0, acc0)
        GROUP(c0.x, c1.x, c2.x, cn.x, d0.x, d1.x, d2.x, dn.x,
              X10, X11, X12, PX1, Y10, Y11, Y12, PY1, acc1)
        GROUP(c0.y, c1.y, c2.y, cn.y, d0.y, d1.y, d2.y, dn.y,
              X00, X01, X02, PX0, Y00, Y01, Y02, PY0, acc0)
        GROUP(c0.y, c1.y, c2.y, cn.y, d0.y, d1.y, d2.y, dn.y,
              X10, X11, X12, PX1, Y10, Y11, Y12, PY1, acc1)
        GROUP(c0.z, c1.z, c2.z, cn.z, d0.z, d1.z, d2.z, dn.z,
              X00, X01, X02, PX0, Y00, Y01, Y02, PY0, acc0)
        GROUP(c0.z, c1.z, c2.z, cn.z, d0.z, d1.z, d2.z, dn.z,
              X10, X11, X12, PX1, Y10, Y11, Y12, PY1, acc1)
        GROUP(c0.w, c1.w, c2.w, cn.w, d0.w, d1.w, d2.w, dn.w,
              X00, X01, X02, PX0, Y00, Y01, Y02, PY0, acc0)
        GROUP(c0.w, c1.w, c2.w, cn.w, d0.w, d1.w, d2.w, dn.w,
              X10, X11, X12, PX1, Y10, Y11, Y12, PY1, acc1)
    }
    #undef GROUP

    float v0l, v0h, v1l, v1h;
    unpack2(acc0, v0l, v0h);
    unpack2(acc1, v1l, v1h);
    float val = (v0l + v0h) + (v1l + v1h);

    // deterministic block reduce (8 warps)
    #pragma unroll
    for (int off = 16; off > 0; off >>= 1)
        val += __shfl_down_sync(0xffffffffu, val, off);
    __shared__ float wsum[TPB / 32];
    if ((tid & 31) == 0) wsum[tid >> 5] = val;
    __syncthreads();
    if (tid == 0) {
        float s = 0.f;
        #pragma unroll
        for (int ww = 0; ww < TPB / 32; ww++) s += wsum[ww];
        g_part[bid] = diag ? s : 2.0f * s;
    }

    // ---- last-block final reduction ----
    __shared__ bool isLast;
    if (tid == 0) {
        __threadfence();
        unsigned v = atomicAdd(&g_count, 1u);
        isLast = (v == (unsigned)(gridDim.x - 1));
    }
    __syncthreads();
    if (!isLast) return;
    __threadfence();

    int b2 = tid >> 5;                  // 0..7 (batch per warp)
    int l  = tid & 31;

    float wacc = 0.f;
    for (int k = l; k < TPAIRS; k += 32)
        wacc += g_part[b2 * TPAIRS + k];
    float a[9];
    #pragma unroll
    for (int q = 0; q < 9; q++)
        a[q] = (l < NT) ? g_aux[b2][l][q] : 0.f;

    #pragma unroll
    for (int off = 16; off > 0; off >>= 1) {
        wacc += __shfl_down_sync(0xffffffffu, wacc, off);
        #pragma unroll
        for (int q = 0; q < 9; q++)
            a[q] += __shfl_down_sync(0xffffffffu, a[q], off);
    }

    __shared__ float norms[BATCH];
    if (l == 0) {
        float n = (float)NPTS;
        float T = 2.0f * (n * a[0] - (a[1] * a[1] + a[2] * a[2] + a[3] * a[3]))
                + 2.0f * (n * a[4] - (a[5] * a[5] + a[6] * a[6] + a[7] * a[7]));
        float W = wacc - 2.0f * a[8];
        float S = T - 2.0f * W;
        if (S < 0.f) S = 0.f;
        norms[b2] = sqrtf(S);
    }
    __syncthreads();
    if (tid == 0) {
        float tot = 0.f;
        #pragma unroll
        for (int i = 0; i < BATCH; i++) tot += norms[i];
        float n = (float)NPTS;
        out[0] = tot / sqrtf(n * n - n) / (float)BATCH;
        g_count = 0;                    // reset for graph replay
        g_prep  = 0;
    }
}

extern "C" void kernel_launch(void* const* d_in, const int* in_sizes, int n_in,
                              void* d_out, int out_size) {
    const float* x = (const float*)d_in[0];
    const float* y = (const float*)d_in[1];
    (void)in_sizes; (void)n_in; (void)out_size;
    drmsd_kernel<<<NBLK, TPB>>>(x, y, (float*)d_out);
}